// round 10
// baseline (speedup 1.0000x reference)
#include <cuda_runtime.h>
#include <math.h>

#define B_  16
#define L_  4096
#define D_  512
#define LP1 (L_ + 1)

#define ROWS_PER_BLK 8   // blockDim = (128, 8) = 1024 threads, grid 513

// fp[d] = f32(100^{-(d - d%2)/D}) + f32(pi/2)*(d%2), generated at COMPILE
// TIME via double pow-by-squaring (validated bit-identical across R3-R9).
struct FpTable { float v[D_]; };

constexpr FpTable make_fp() {
    FpTable t{};
    const double b = 0.9821718891880367;   // 100^(-1/256), correctly rounded
    const float  PI2F = 1.57079637050628662109375f;  // float(pi/2)
    for (int d4 = 0; d4 < D_ / 4; d4++) {
        double p = 1.0, bs = b * b;        // p = b^(2*d4)
        int k = d4;
        for (int i = 0; i < 7; i++) {
            if (k & 1) p *= bs;
            bs *= bs;
            k >>= 1;
        }
        float f0 = (float)p;               // freq at d = 4*d4
        float f1 = (float)(p * b);         // freq at d = 4*d4+2
        t.v[4 * d4 + 0] = f0;
        t.v[4 * d4 + 1] = f0 + PI2F;
        t.v[4 * d4 + 2] = f1;
        t.v[4 * d4 + 3] = f1 + PI2F;
    }
    return t;
}

// Baked into the cubin; L1-resident load in-kernel. No setup node needed.
__device__ constexpr FpTable g_fp = make_fp();

// sin of the f32 angle l*fp (angle formed in f32 exactly like the reference),
// with double-precision Cody-Waite reduction so correctness is independent of
// --use_fast_math (naked sinf would become __sinf and blow up at |x| ~ 1e4).
__device__ __forceinline__ float emb_sin(float lf, float fp) {
    float x = __fmul_rn(lf, fp);                 // matches ref's f32 product
    double xd = (double)x;
    double k  = rint(xd * 0.15915494309189533576888376337251);  // 1/(2*pi)
    double r  = fma(-k, 6.283185307179586476925286766559, xd);  // |r| <= pi
    return sinf((float)r);                        // small-arg: cheap & exact
}

// ===== EXACT R1/R5/R9 kernel body (fastest measured: 32.5us, regs=32),
// with 8 rows per block (per-thread instruction stream unchanged). ==========
__global__ __launch_bounds__(1024)
void pe_kernel(const float* __restrict__ tokens,
               const int*   __restrict__ lengths,
               const float* __restrict__ cls,
               float*       __restrict__ out) {
    // One row per 128 threads (float4 over D=512); 8 rows per block.
    int row = blockIdx.x * ROWS_PER_BLK + threadIdx.y;
    if (row > L_) return;

    int d4 = threadIdx.x;                 // float4 index within the row
    int dd = d4 * 4;

    float4 fp   = *reinterpret_cast<const float4*>(g_fp.v + dd);
    float4 cls4 = *reinterpret_cast<const float4*>(cls    + dd);

    // Positional embedding for this (row, dd..dd+3) — computed ONCE, reused
    // across all 16 batch elements. Row L has no embedding.
    float4 emb = make_float4(0.f, 0.f, 0.f, 0.f);
    if (row < L_) {
        float lf = (float)row;
        emb.x = emb_sin(lf, fp.x);
        emb.y = emb_sin(lf, fp.y);
        emb.z = emb_sin(lf, fp.z);
        emb.w = emb_sin(lf, fp.w);
    }

    int lens[B_];
#pragma unroll
    for (int b = 0; b < B_; b++) lens[b] = __ldg(lengths + b);

#pragma unroll
    for (int b = 0; b < B_; b++) {
        float4 o;
        if (row < lens[b]) {
            // valid token: tokens + emb
            const float4 t = *reinterpret_cast<const float4*>(
                tokens + ((size_t)b * L_ + row) * D_ + dd);
            o = make_float4(t.x + emb.x, t.y + emb.y, t.z + emb.z, t.w + emb.w);
        } else if (row == lens[b]) {
            // CLS row (x was zeroed here in the reference, so out = cls)
            o = cls4;
        } else {
            o = make_float4(0.f, 0.f, 0.f, 0.f);
        }
        *reinterpret_cast<float4*>(
            out + ((size_t)b * LP1 + row) * D_ + dd) = o;
    }
}

extern "C" void kernel_launch(void* const* d_in, const int* in_sizes, int n_in,
                              void* d_out, int out_size) {
    const float* tokens  = (const float*)d_in[0];  // [B, L, D] f32
    const int*   lengths = (const int*)  d_in[1];  // [B] i32
    const float* cls     = (const float*)d_in[2];  // [D] f32
    float*       out     = (float*)d_out;          // [B, L+1, D] f32

    (void)in_sizes; (void)n_in; (void)out_size;

    dim3 blk(128, ROWS_PER_BLK);
    int grid = (LP1 + ROWS_PER_BLK - 1) / ROWS_PER_BLK;  // 513 blocks
    pe_kernel<<<grid, blk>>>(tokens, lengths, cls, out);
}

// round 11
// speedup vs baseline: 1.1042x; 1.1042x over previous
#include <cuda_runtime.h>
#include <math.h>

#define B_  16
#define L_  4096
#define D_  512
#define LP1 (L_ + 1)

// fp[d] = f32(100^{-(d - d%2)/D}) + f32(pi/2)*(d%2), generated at COMPILE
// TIME via double pow-by-squaring (validated bit-identical across R3-R10).
struct FpTable { float v[D_]; };

constexpr FpTable make_fp() {
    FpTable t{};
    const double b = 0.9821718891880367;   // 100^(-1/256), correctly rounded
    const float  PI2F = 1.57079637050628662109375f;  // float(pi/2)
    for (int d4 = 0; d4 < D_ / 4; d4++) {
        double p = 1.0, bs = b * b;        // p = b^(2*d4)
        int k = d4;
        for (int i = 0; i < 7; i++) {
            if (k & 1) p *= bs;
            bs *= bs;
            k >>= 1;
        }
        float f0 = (float)p;               // freq at d = 4*d4
        float f1 = (float)(p * b);         // freq at d = 4*d4+2
        t.v[4 * d4 + 0] = f0;
        t.v[4 * d4 + 1] = f0 + PI2F;
        t.v[4 * d4 + 2] = f1;
        t.v[4 * d4 + 3] = f1 + PI2F;
    }
    return t;
}

// Baked into the cubin; L1-resident load in-kernel. No setup node needed.
__device__ constexpr FpTable g_fp = make_fp();

// sin of the f32 angle l*fp (angle formed in f32 exactly like the reference),
// with double-precision Cody-Waite reduction so correctness is independent of
// --use_fast_math (naked sinf would become __sinf and blow up at |x| ~ 1e4).
__device__ __forceinline__ float emb_sin(float lf, float fp) {
    float x = __fmul_rn(lf, fp);                 // matches ref's f32 product
    double xd = (double)x;
    double k  = rint(xd * 0.15915494309189533576888376337251);  // 1/(2*pi)
    double r  = fma(-k, 6.283185307179586476925286766559, xd);  // |r| <= pi
    return sinf((float)r);                        // small-arg: cheap & exact
}

// ===== Converged optimum (R9): flat body, regs=32, (128,4) x 1025 blocks.
// Kernel = 32.5us ~= 95-97% of the ~6.3TB/s effective-traffic ceiling.
// Every structural variant tried in R2-R8/R10 measured slower. =============
__global__ __launch_bounds__(512)
void pe_kernel(const float* __restrict__ tokens,
               const int*   __restrict__ lengths,
               const float* __restrict__ cls,
               float*       __restrict__ out) {
    // One row per warp: 128 threads cover D=512 via float4.
    // blockDim = (128, 4) -> 4 rows per block. Rows 0..L inclusive.
    int row = blockIdx.x * 4 + threadIdx.y;
    if (row > L_) return;

    int d4 = threadIdx.x;                 // float4 index within the row
    int dd = d4 * 4;

    float4 fp   = *reinterpret_cast<const float4*>(g_fp.v + dd);
    float4 cls4 = *reinterpret_cast<const float4*>(cls    + dd);

    // Positional embedding for this (row, dd..dd+3) — computed ONCE, reused
    // across all 16 batch elements. Row L has no embedding.
    float4 emb = make_float4(0.f, 0.f, 0.f, 0.f);
    if (row < L_) {
        float lf = (float)row;
        emb.x = emb_sin(lf, fp.x);
        emb.y = emb_sin(lf, fp.y);
        emb.z = emb_sin(lf, fp.z);
        emb.w = emb_sin(lf, fp.w);
    }

    int lens[B_];
#pragma unroll
    for (int b = 0; b < B_; b++) lens[b] = __ldg(lengths + b);

#pragma unroll
    for (int b = 0; b < B_; b++) {
        float4 o;
        if (row < lens[b]) {
            // valid token: tokens + emb
            const float4 t = *reinterpret_cast<const float4*>(
                tokens + ((size_t)b * L_ + row) * D_ + dd);
            o = make_float4(t.x + emb.x, t.y + emb.y, t.z + emb.z, t.w + emb.w);
        } else if (row == lens[b]) {
            // CLS row (x was zeroed here in the reference, so out = cls)
            o = cls4;
        } else {
            o = make_float4(0.f, 0.f, 0.f, 0.f);
        }
        *reinterpret_cast<float4*>(
            out + ((size_t)b * LP1 + row) * D_ + dd) = o;
    }
}

extern "C" void kernel_launch(void* const* d_in, const int* in_sizes, int n_in,
                              void* d_out, int out_size) {
    const float* tokens  = (const float*)d_in[0];  // [B, L, D] f32
    const int*   lengths = (const int*)  d_in[1];  // [B] i32
    const float* cls     = (const float*)d_in[2];  // [D] f32
    float*       out     = (float*)d_out;          // [B, L+1, D] f32

    (void)in_sizes; (void)n_in; (void)out_size;

    dim3 blk(128, 4);
    int grid = (LP1 + 3) / 4;                      // 1025 blocks, rows 0..4096
    pe_kernel<<<grid, blk>>>(tokens, lengths, cls, out);
}

// round 12
// speedup vs baseline: 1.1476x; 1.0393x over previous
#include <cuda_runtime.h>
#include <math.h>

#define B_  16
#define L_  4096
#define D_  512
#define LP1 (L_ + 1)

#define ROWS_PER_BLK 2   // blockDim = (128, 2) = 256 threads, grid 2049

// fp[d] = f32(100^{-(d - d%2)/D}) + f32(pi/2)*(d%2), generated at COMPILE
// TIME via double pow-by-squaring (validated bit-identical across R3-R11).
struct FpTable { float v[D_]; };

constexpr FpTable make_fp() {
    FpTable t{};
    const double b = 0.9821718891880367;   // 100^(-1/256), correctly rounded
    const float  PI2F = 1.57079637050628662109375f;  // float(pi/2)
    for (int d4 = 0; d4 < D_ / 4; d4++) {
        double p = 1.0, bs = b * b;        // p = b^(2*d4)
        int k = d4;
        for (int i = 0; i < 7; i++) {
            if (k & 1) p *= bs;
            bs *= bs;
            k >>= 1;
        }
        float f0 = (float)p;               // freq at d = 4*d4
        float f1 = (float)(p * b);         // freq at d = 4*d4+2
        t.v[4 * d4 + 0] = f0;
        t.v[4 * d4 + 1] = f0 + PI2F;
        t.v[4 * d4 + 2] = f1;
        t.v[4 * d4 + 3] = f1 + PI2F;
    }
    return t;
}

// Baked into the cubin; L1-resident load in-kernel. No setup node needed.
__device__ constexpr FpTable g_fp = make_fp();

// sin of the f32 angle l*fp (angle formed in f32 exactly like the reference),
// with double-precision Cody-Waite reduction so correctness is independent of
// --use_fast_math (naked sinf would become __sinf and blow up at |x| ~ 1e4).
__device__ __forceinline__ float emb_sin(float lf, float fp) {
    float x = __fmul_rn(lf, fp);                 // matches ref's f32 product
    double xd = (double)x;
    double k  = rint(xd * 0.15915494309189533576888376337251);  // 1/(2*pi)
    double r  = fma(-k, 6.283185307179586476925286766559, xd);  // |r| <= pi
    return sinf((float)r);                        // small-arg: cheap & exact
}

// ===== EXACT R9/R11 body (kernel 32.5-33.8us, regs=32), with 2 rows per
// block: per-thread instruction stream unchanged; finer CTA granularity. ====
__global__ __launch_bounds__(256)
void pe_kernel(const float* __restrict__ tokens,
               const int*   __restrict__ lengths,
               const float* __restrict__ cls,
               float*       __restrict__ out) {
    // One row per warp: 128 threads cover D=512 via float4; 2 rows/block.
    int row = blockIdx.x * ROWS_PER_BLK + threadIdx.y;
    if (row > L_) return;

    int d4 = threadIdx.x;                 // float4 index within the row
    int dd = d4 * 4;

    float4 fp   = *reinterpret_cast<const float4*>(g_fp.v + dd);
    float4 cls4 = *reinterpret_cast<const float4*>(cls    + dd);

    // Positional embedding for this (row, dd..dd+3) — computed ONCE, reused
    // across all 16 batch elements. Row L has no embedding.
    float4 emb = make_float4(0.f, 0.f, 0.f, 0.f);
    if (row < L_) {
        float lf = (float)row;
        emb.x = emb_sin(lf, fp.x);
        emb.y = emb_sin(lf, fp.y);
        emb.z = emb_sin(lf, fp.z);
        emb.w = emb_sin(lf, fp.w);
    }

    int lens[B_];
#pragma unroll
    for (int b = 0; b < B_; b++) lens[b] = __ldg(lengths + b);

#pragma unroll
    for (int b = 0; b < B_; b++) {
        float4 o;
        if (row < lens[b]) {
            // valid token: tokens + emb
            const float4 t = *reinterpret_cast<const float4*>(
                tokens + ((size_t)b * L_ + row) * D_ + dd);
            o = make_float4(t.x + emb.x, t.y + emb.y, t.z + emb.z, t.w + emb.w);
        } else if (row == lens[b]) {
            // CLS row (x was zeroed here in the reference, so out = cls)
            o = cls4;
        } else {
            o = make_float4(0.f, 0.f, 0.f, 0.f);
        }
        *reinterpret_cast<float4*>(
            out + ((size_t)b * LP1 + row) * D_ + dd) = o;
    }
}

extern "C" void kernel_launch(void* const* d_in, const int* in_sizes, int n_in,
                              void* d_out, int out_size) {
    const float* tokens  = (const float*)d_in[0];  // [B, L, D] f32
    const int*   lengths = (const int*)  d_in[1];  // [B] i32
    const float* cls     = (const float*)d_in[2];  // [D] f32
    float*       out     = (float*)d_out;          // [B, L+1, D] f32

    (void)in_sizes; (void)n_in; (void)out_size;

    dim3 blk(128, ROWS_PER_BLK);
    int grid = (LP1 + ROWS_PER_BLK - 1) / ROWS_PER_BLK;  // 2049 blocks
    pe_kernel<<<grid, blk>>>(tokens, lengths, cls, out);
}

// round 13
// speedup vs baseline: 1.1739x; 1.0230x over previous
#include <cuda_runtime.h>
#include <math.h>

#define B_  16
#define L_  4096
#define D_  512
#define LP1 (L_ + 1)

// blockDim = 128 (one row per CTA), grid 4097: finest CTA granularity.
// R10 (1024 thr) < R9/R11 (512 thr) < R12 (256 thr) in total time — testing
// the next point on the monotone-improving axis.

// fp[d] = f32(100^{-(d - d%2)/D}) + f32(pi/2)*(d%2), generated at COMPILE
// TIME via double pow-by-squaring (validated bit-identical across R3-R12).
struct FpTable { float v[D_]; };

constexpr FpTable make_fp() {
    FpTable t{};
    const double b = 0.9821718891880367;   // 100^(-1/256), correctly rounded
    const float  PI2F = 1.57079637050628662109375f;  // float(pi/2)
    for (int d4 = 0; d4 < D_ / 4; d4++) {
        double p = 1.0, bs = b * b;        // p = b^(2*d4)
        int k = d4;
        for (int i = 0; i < 7; i++) {
            if (k & 1) p *= bs;
            bs *= bs;
            k >>= 1;
        }
        float f0 = (float)p;               // freq at d = 4*d4
        float f1 = (float)(p * b);         // freq at d = 4*d4+2
        t.v[4 * d4 + 0] = f0;
        t.v[4 * d4 + 1] = f0 + PI2F;
        t.v[4 * d4 + 2] = f1;
        t.v[4 * d4 + 3] = f1 + PI2F;
    }
    return t;
}

// Baked into the cubin; L1-resident load in-kernel. No setup node needed.
__device__ constexpr FpTable g_fp = make_fp();

// sin of the f32 angle l*fp (angle formed in f32 exactly like the reference),
// with double-precision Cody-Waite reduction so correctness is independent of
// --use_fast_math (naked sinf would become __sinf and blow up at |x| ~ 1e4).
__device__ __forceinline__ float emb_sin(float lf, float fp) {
    float x = __fmul_rn(lf, fp);                 // matches ref's f32 product
    double xd = (double)x;
    double k  = rint(xd * 0.15915494309189533576888376337251);  // 1/(2*pi)
    double r  = fma(-k, 6.283185307179586476925286766559, xd);  // |r| <= pi
    return sinf((float)r);                        // small-arg: cheap & exact
}

// ===== EXACT R9/R11/R12 body (kernel 32.5-33.8us, regs=32), one row per
// 128-thread CTA: per-thread instruction stream unchanged. ==================
__global__ __launch_bounds__(128)
void pe_kernel(const float* __restrict__ tokens,
               const int*   __restrict__ lengths,
               const float* __restrict__ cls,
               float*       __restrict__ out) {
    // 128 threads cover D=512 via float4; one row per CTA (rows 0..L).
    int row = blockIdx.x;
    if (row > L_) return;

    int d4 = threadIdx.x;                 // float4 index within the row
    int dd = d4 * 4;

    float4 fp   = *reinterpret_cast<const float4*>(g_fp.v + dd);
    float4 cls4 = *reinterpret_cast<const float4*>(cls    + dd);

    // Positional embedding for this (row, dd..dd+3) — computed ONCE, reused
    // across all 16 batch elements. Row L has no embedding.
    float4 emb = make_float4(0.f, 0.f, 0.f, 0.f);
    if (row < L_) {
        float lf = (float)row;
        emb.x = emb_sin(lf, fp.x);
        emb.y = emb_sin(lf, fp.y);
        emb.z = emb_sin(lf, fp.z);
        emb.w = emb_sin(lf, fp.w);
    }

    int lens[B_];
#pragma unroll
    for (int b = 0; b < B_; b++) lens[b] = __ldg(lengths + b);

#pragma unroll
    for (int b = 0; b < B_; b++) {
        float4 o;
        if (row < lens[b]) {
            // valid token: tokens + emb
            const float4 t = *reinterpret_cast<const float4*>(
                tokens + ((size_t)b * L_ + row) * D_ + dd);
            o = make_float4(t.x + emb.x, t.y + emb.y, t.z + emb.z, t.w + emb.w);
        } else if (row == lens[b]) {
            // CLS row (x was zeroed here in the reference, so out = cls)
            o = cls4;
        } else {
            o = make_float4(0.f, 0.f, 0.f, 0.f);
        }
        *reinterpret_cast<float4*>(
            out + ((size_t)b * LP1 + row) * D_ + dd) = o;
    }
}

extern "C" void kernel_launch(void* const* d_in, const int* in_sizes, int n_in,
                              void* d_out, int out_size) {
    const float* tokens  = (const float*)d_in[0];  // [B, L, D] f32
    const int*   lengths = (const int*)  d_in[1];  // [B] i32
    const float* cls     = (const float*)d_in[2];  // [D] f32
    float*       out     = (float*)d_out;          // [B, L+1, D] f32

    (void)in_sizes; (void)n_in; (void)out_size;

    pe_kernel<<<LP1, 128>>>(tokens, lengths, cls, out);  // 4097 blocks
}